// round 10
// baseline (speedup 1.0000x reference)
#include <cuda_runtime.h>
#include <cuda_bf16.h>
#include <math.h>
#include <stdint.h>

#define N 8192
#define FIN 256
#define FOUT 64
#define NSPLIT 8    // j-splits per i-tile
#define NTILE 128   // i-rows per CTA
#define NSB 8       // 128-j supersteps per CTA (1024 j per split)

// ---------------- device scratch ----------------
__device__ float    g_Wh[(size_t)N * FOUT];
__device__ uint4    g_Bfrag[512 * 2 * 4 * 32];      // tf32 B fragments, 2 MB
__device__ unsigned g_mask[(size_t)N * 256];        // 8 MB bit-packed adj
__device__ float    g_E1[N];
__device__ float    g_E2[N];
__device__ float    g_fsrc[N];
__device__ unsigned g_gmax_enc;
__device__ float    g_Dpart[NSPLIT][(size_t)N * FOUT];
__device__ float    g_lpart[NSPLIT][N];

// ---------------- helpers ----------------
__device__ __forceinline__ uint32_t f2tf32(float x) {
    uint32_t r;
    asm("cvt.rna.tf32.f32 %0, %1;" : "=r"(r) : "f"(x));
    return r;
}
__device__ __forceinline__ void mma_tf32(float* d, uint32_t a0, uint32_t a1,
                                         uint32_t a2, uint32_t a3, uint32_t b0,
                                         uint32_t b1) {
    asm volatile(
        "mma.sync.aligned.m16n8k8.row.col.f32.tf32.tf32.f32 "
        "{%0,%1,%2,%3}, {%4,%5,%6,%7}, {%8,%9}, {%0,%1,%2,%3};"
        : "+f"(d[0]), "+f"(d[1]), "+f"(d[2]), "+f"(d[3])
        : "r"(a0), "r"(a1), "r"(a2), "r"(a3), "r"(b0), "r"(b1));
}
__device__ __forceinline__ unsigned enc_f(float x) {
    unsigned b = __float_as_uint(x);
    return (b & 0x80000000u) ? ~b : (b | 0x80000000u);
}
__device__ __forceinline__ float dec_f(unsigned k) {
    return __uint_as_float((k & 0x80000000u) ? (k & 0x7fffffffu) : ~k);
}

// ---------------------------------------------------------------------------
// Kernel M: bit-pack adjacency. Warp handles 2 tasks (r, sb); lane loads
// uint4 adj[r][sb*128 + 4*lane .. +3]; ballots build 4 mask words:
//   g_mask[r*256 + sb*4 + comp] bit q  <=>  adj[r][sb*128 + 4q + comp] != 0
// Both loads issued before ballots for MLP=2.
// ---------------------------------------------------------------------------
__global__ __launch_bounds__(256) void mask_kernel(const int* __restrict__ adj) {
    const int wid = blockIdx.x * 8 + (threadIdx.x >> 5);  // 0..262143
    const int lane = threadIdx.x & 31;
    const int t0 = wid * 2, t1 = wid * 2 + 1;
    const int r0 = t0 >> 6, sb0 = t0 & 63;
    const int r1 = t1 >> 6, sb1 = t1 & 63;
    const uint4 v0 =
        *(const uint4*)(adj + (size_t)r0 * N + sb0 * 128 + lane * 4);
    const uint4 v1 =
        *(const uint4*)(adj + (size_t)r1 * N + sb1 * 128 + lane * 4);
    const unsigned a0 = __ballot_sync(~0u, v0.x != 0);
    const unsigned a1 = __ballot_sync(~0u, v0.y != 0);
    const unsigned a2 = __ballot_sync(~0u, v0.z != 0);
    const unsigned a3 = __ballot_sync(~0u, v0.w != 0);
    const unsigned b0 = __ballot_sync(~0u, v1.x != 0);
    const unsigned b1 = __ballot_sync(~0u, v1.y != 0);
    const unsigned b2 = __ballot_sync(~0u, v1.z != 0);
    const unsigned b3 = __ballot_sync(~0u, v1.w != 0);
    if (lane == 0) {
        *(uint4*)&g_mask[(size_t)r0 * 256 + sb0 * 4] = make_uint4(a0, a1, a2, a3);
        *(uint4*)&g_mask[(size_t)r1 * 256 + sb1 * 4] = make_uint4(b0, b1, b2, b3);
    }
}

// ---------------------------------------------------------------------------
// Kernel A: Wh = h @ W. k-outer/r-inner (Ws reuse across 4 rows).
// ---------------------------------------------------------------------------
__global__ __launch_bounds__(256, 4) void wh_kernel(const float* __restrict__ h,
                                                    const float* __restrict__ W) {
    __shared__ float Ws[128][FOUT];
    if (blockIdx.x == 0 && threadIdx.x == 0) g_gmax_enc = 0u;
    const int f = threadIdx.x & 63;
    const int g = threadIdx.x >> 6;
    const int row0 = blockIdx.x * 16 + g * 4;
    float acc0 = 0.f, acc1 = 0.f, acc2 = 0.f, acc3 = 0.f;
    for (int t = 0; t < 2; t++) {
        __syncthreads();
        for (int idx = threadIdx.x; idx < 128 * FOUT; idx += 256)
            (&Ws[0][0])[idx] = W[t * 128 * FOUT + idx];
        __syncthreads();
        const float4* h0 = (const float4*)(h + (size_t)(row0 + 0) * FIN + t * 128);
        const float4* h1 = (const float4*)(h + (size_t)(row0 + 1) * FIN + t * 128);
        const float4* h2 = (const float4*)(h + (size_t)(row0 + 2) * FIN + t * 128);
        const float4* h3 = (const float4*)(h + (size_t)(row0 + 3) * FIN + t * 128);
#pragma unroll 8
        for (int k4 = 0; k4 < 32; k4++) {
            const float4 v0 = h0[k4], v1 = h1[k4], v2 = h2[k4], v3 = h3[k4];
            const float w0 = Ws[k4 * 4 + 0][f];
            const float w1 = Ws[k4 * 4 + 1][f];
            const float w2 = Ws[k4 * 4 + 2][f];
            const float w3 = Ws[k4 * 4 + 3][f];
            acc0 += v0.x * w0 + v0.y * w1 + v0.z * w2 + v0.w * w3;
            acc1 += v1.x * w0 + v1.y * w1 + v1.z * w2 + v1.w * w3;
            acc2 += v2.x * w0 + v2.y * w1 + v2.z * w2 + v2.w * w3;
            acc3 += v3.x * w0 + v3.y * w1 + v3.z * w2 + v3.w * w3;
        }
    }
    g_Wh[(size_t)(row0 + 0) * FOUT + f] = acc0;
    g_Wh[(size_t)(row0 + 1) * FOUT + f] = acc1;
    g_Wh[(size_t)(row0 + 2) * FOUT + f] = acc2;
    g_Wh[(size_t)(row0 + 3) * FOUT + f] = acc3;
}

// ---------------------------------------------------------------------------
// Kernel B: f_src, E1=exp(f_dst), E2=exp(0.2 f_dst), fused global max(f_dst).
// ---------------------------------------------------------------------------
__global__ __launch_bounds__(256) void fvec_kernel(const float* __restrict__ a) {
    __shared__ unsigned smax[8];
    const int i = blockIdx.x * blockDim.x + threadIdx.x;
    const float4* w4 = (const float4*)(g_Wh + (size_t)i * FOUT);
    const float4* a4 = (const float4*)a;
    float s = 0.f, d = 0.f;
#pragma unroll
    for (int q = 0; q < 16; q++) {
        float4 v = w4[q], as_ = a4[q], ad = a4[16 + q];
        s += v.x * as_.x + v.y * as_.y + v.z * as_.z + v.w * as_.w;
        d += v.x * ad.x + v.y * ad.y + v.z * ad.z + v.w * ad.w;
    }
    g_fsrc[i] = s;
    g_E1[i] = __expf(d);
    g_E2[i] = __expf(0.2f * d);
    unsigned k = enc_f(d);
#pragma unroll
    for (int off = 16; off > 0; off >>= 1)
        k = max(k, __shfl_xor_sync(0xffffffffu, k, off));
    if ((threadIdx.x & 31) == 0) smax[threadIdx.x >> 5] = k;
    __syncthreads();
    if (threadIdx.x == 0) {
        unsigned m = smax[0];
#pragma unroll
        for (int w = 1; w < 8; w++) m = max(m, smax[w]);
        atomicMax(&g_gmax_enc, m);
    }
}

// ---------------------------------------------------------------------------
// Kernel B2: build tf32 B fragments of Wh for mma.m16n8k8.
// ---------------------------------------------------------------------------
__global__ __launch_bounds__(256) void bfrag_kernel() {
    const int wid = blockIdx.x * 8 + (threadIdx.x >> 5);  // 0..4095
    const int lane = threadIdx.x & 31;
    const int jblock = wid >> 3, kh = (wid >> 2) & 1, ntp = wid & 3;
    const int j0 = jblock * 16 + kh * 8;
    const int f0 = ntp * 16;
    const int g = lane >> 2, tc = lane & 3;
    uint4 b;
    b.x = f2tf32(g_Wh[(size_t)(j0 + tc) * FOUT + f0 + g]);
    b.y = f2tf32(g_Wh[(size_t)(j0 + tc + 4) * FOUT + f0 + g]);
    b.z = f2tf32(g_Wh[(size_t)(j0 + tc) * FOUT + f0 + 8 + g]);
    b.w = f2tf32(g_Wh[(size_t)(j0 + tc + 4) * FOUT + f0 + 8 + g]);
    g_Bfrag[(size_t)wid * 32 + lane] = b;
}

// ---------------------------------------------------------------------------
// Kernel C (main): D[128,64] += P[128,1024] @ Wh[1024,64] via mma.tf32.
// adj comes from bit-packed g_mask (8 MB, L2-resident, read once):
//   thread (g, tc) reads word[r][sbg][tc]; col tc+4cq of step si -> bit si*8+cq.
// No cp.async, no smem adj, no CTA syncs in the loop. Masks prefetched one
// superstep ahead.
// ---------------------------------------------------------------------------
__global__ __launch_bounds__(256, 2) void gat_mma_kernel() {
    __shared__ float2 s_E[1024];  // 8 KB
    __shared__ float  sA1[NTILE], sA2[NTILE];

    const int tid = threadIdx.x, lane = tid & 31, warp = tid >> 5;
    const int g = lane >> 2, tc = lane & 3;
    const int it = blockIdx.x >> 3, js = blockIdx.x & 7;
    const int row0 = it * NTILE, jbase = js * 1024;

    // stage E and per-row A1/A2
    for (int k = tid; k < 1024; k += 256)
        s_E[k] = make_float2(g_E1[jbase + k], g_E2[jbase + k]);
    if (tid < NTILE) {
        const float fs = g_fsrc[row0 + tid];
        float M = fs + dec_f(g_gmax_enc);
        M = M > 0.f ? M : 0.2f * M;  // lrelu monotone -> valid row upper bound
        sA1[tid] = __expf(fs - M);
        sA2[tid] = __expf(0.2f * fs - M);
    }
    __syncthreads();

    const int lr0 = warp * 16 + g, lr1 = lr0 + 8;
    const int gr0 = row0 + lr0, gr1 = row0 + lr1;
    const float A1r0 = sA1[lr0], A2r0 = sA2[lr0];
    const float A1r1 = sA1[lr1], A2r1 = sA2[lr1];

    // mask pointers: word index = r*256 + sbg*4 + tc, sbg = js*8 + sb
    const unsigned* mp0 = g_mask + (size_t)gr0 * 256 + js * 32 + tc;
    const unsigned* mp1 = g_mask + (size_t)gr1 * 256 + js * 32 + tc;

    float d[8][4];
#pragma unroll
    for (int nt = 0; nt < 8; nt++)
#pragma unroll
        for (int q = 0; q < 4; q++) d[nt][q] = 0.f;
    float l0 = 0.f, l1 = 0.f;

    unsigned m0 = mp0[0], m1 = mp1[0];

    for (int sb = 0; sb < NSB; sb++) {
        unsigned n0, n1;
        if (sb < NSB - 1) {  // prefetch next superstep's masks
            n0 = mp0[(sb + 1) * 4];
            n1 = mp1[(sb + 1) * 4];
        }
#pragma unroll
        for (int si = 0; si < 4; si++) {
            const int s = sb * 4 + si;
            const int jl = s * 32;

            // ---- p for 2 rows x 8 cols {tc + 4cq}; bit si*8+cq of mask ----
            float p0[8], p1[8];
#pragma unroll
            for (int cq = 0; cq < 8; cq++) {
                const float2 e = s_E[jl + tc + cq * 4];
                const float v0 = fmaxf(A1r0 * e.x, A2r0 * e.y);
                const float v1 = fmaxf(A1r1 * e.x, A2r1 * e.y);
                p0[cq] = ((m0 >> (si * 8 + cq)) & 1u) ? v0 : 0.f;
                p1[cq] = ((m1 >> (si * 8 + cq)) & 1u) ? v1 : 0.f;
                l0 += p0[cq];
                l1 += p1[cq];
            }

            // ---- 4 K-groups of 8 j: MMAs (B fragments from L2) ----
#pragma unroll
            for (int kk = 0; kk < 4; kk++) {
                const int jblock = js * 64 + 2 * s + (kk >> 1);
                const int kh = kk & 1;
                const uint4* bp =
                    &g_Bfrag[(size_t)((jblock * 2 + kh) * 4) * 32 + lane];
                const uint32_t a0 = f2tf32(p0[kk * 2]);
                const uint32_t a1 = f2tf32(p1[kk * 2]);
                const uint32_t a2 = f2tf32(p0[kk * 2 + 1]);
                const uint32_t a3 = f2tf32(p1[kk * 2 + 1]);
                const uint4 B0 = bp[0];
                const uint4 B1 = bp[32];
                const uint4 B2 = bp[64];
                const uint4 B3 = bp[96];
                mma_tf32(d[0], a0, a1, a2, a3, B0.x, B0.y);
                mma_tf32(d[1], a0, a1, a2, a3, B0.z, B0.w);
                mma_tf32(d[2], a0, a1, a2, a3, B1.x, B1.y);
                mma_tf32(d[3], a0, a1, a2, a3, B1.z, B1.w);
                mma_tf32(d[4], a0, a1, a2, a3, B2.x, B2.y);
                mma_tf32(d[5], a0, a1, a2, a3, B2.z, B2.w);
                mma_tf32(d[6], a0, a1, a2, a3, B3.x, B3.y);
                mma_tf32(d[7], a0, a1, a2, a3, B3.z, B3.w);
            }
        }
        m0 = n0;
        m1 = n1;
    }

    // write D partials
#pragma unroll
    for (int nt = 0; nt < 8; nt++) {
        const int f = nt * 8 + 2 * tc;
        *(float2*)&g_Dpart[js][(size_t)gr0 * FOUT + f] =
            make_float2(d[nt][0], d[nt][1]);
        *(float2*)&g_Dpart[js][(size_t)gr1 * FOUT + f] =
            make_float2(d[nt][2], d[nt][3]);
    }
    // row sums: reduce over tc (lanes g*4..g*4+3)
    l0 += __shfl_xor_sync(0xffffffffu, l0, 1);
    l0 += __shfl_xor_sync(0xffffffffu, l0, 2);
    l1 += __shfl_xor_sync(0xffffffffu, l1, 1);
    l1 += __shfl_xor_sync(0xffffffffu, l1, 2);
    if (tc == 0) {
        g_lpart[js][gr0] = l0;
        g_lpart[js][gr1] = l1;
    }
}

// ---------------------------------------------------------------------------
// Kernel E: combine partials, divide, ELU.
// ---------------------------------------------------------------------------
__global__ __launch_bounds__(256) void fixup_kernel(float* __restrict__ out) {
    const int idx = blockIdx.x * 256 + threadIdx.x;
    const int i = idx >> 4;
    const int f4 = (idx & 15) * 4;
    float4 acc = make_float4(0.f, 0.f, 0.f, 0.f);
    float l = 0.f;
#pragma unroll
    for (int js = 0; js < NSPLIT; js++) {
        const float4 dv = *(const float4*)&g_Dpart[js][(size_t)i * FOUT + f4];
        acc.x += dv.x; acc.y += dv.y; acc.z += dv.z; acc.w += dv.w;
        l += g_lpart[js][i];
    }
    const float inv = 1.f / l;
    float o0 = acc.x * inv, o1 = acc.y * inv, o2 = acc.z * inv, o3 = acc.w * inv;
    o0 = o0 > 0.f ? o0 : expm1f(o0);
    o1 = o1 > 0.f ? o1 : expm1f(o1);
    o2 = o2 > 0.f ? o2 : expm1f(o2);
    o3 = o3 > 0.f ? o3 : expm1f(o3);
    *(float4*)&out[(size_t)i * FOUT + f4] = make_float4(o0, o1, o2, o3);
}

// ---------------------------------------------------------------------------
extern "C" void kernel_launch(void* const* d_in, const int* in_sizes, int n_in,
                              void* d_out, int out_size) {
    const float* h = (const float*)d_in[0];
    const int* adj = (const int*)d_in[1];
    const float* W = (const float*)d_in[2];
    const float* a = (const float*)d_in[3];
    float* out = (float*)d_out;

    mask_kernel<<<32768, 256>>>(adj);
    wh_kernel<<<N / 16, 256>>>(h, W);
    fvec_kernel<<<N / 256, 256>>>(a);
    bfrag_kernel<<<512, 256>>>();
    gat_mma_kernel<<<(N / NTILE) * NSPLIT, 256>>>();
    fixup_kernel<<<N * 16 / 256, 256>>>(out);
}

// round 11
// speedup vs baseline: 1.2294x; 1.2294x over previous
#include <cuda_runtime.h>
#include <cuda_bf16.h>
#include <math.h>
#include <stdint.h>

#define N 8192
#define FIN 256
#define FOUT 64
#define NSPLIT 8    // j-splits per i-tile
#define NTILE 128   // i-rows per CTA
#define NSB 8       // 128-j supersteps per CTA (1024 j per split)

// ---------------- device scratch ----------------
__device__ float    g_Wh[(size_t)N * FOUT];
__device__ uint4    g_Bfrag[512 * 2 * 4 * 32];  // tf32 B fragments, 2 MB
__device__ unsigned g_mask[(size_t)N * 256];    // 8 MB bit-packed adj
__device__ float    g_E1[N];
__device__ float    g_E2[N];
__device__ float    g_fsrc[N];
__device__ unsigned g_gmax_enc;
__device__ float    g_Dpart[NSPLIT][(size_t)N * FOUT];
__device__ float    g_lpart[NSPLIT][N];

// ---------------- helpers ----------------
__device__ __forceinline__ uint32_t f2tf32(float x) {
    uint32_t r;
    asm("cvt.rna.tf32.f32 %0, %1;" : "=r"(r) : "f"(x));
    return r;
}
__device__ __forceinline__ void mma_tf32(float* d, uint32_t a0, uint32_t a1,
                                         uint32_t a2, uint32_t a3, uint32_t b0,
                                         uint32_t b1) {
    asm volatile(
        "mma.sync.aligned.m16n8k8.row.col.f32.tf32.tf32.f32 "
        "{%0,%1,%2,%3}, {%4,%5,%6,%7}, {%8,%9}, {%0,%1,%2,%3};"
        : "+f"(d[0]), "+f"(d[1]), "+f"(d[2]), "+f"(d[3])
        : "r"(a0), "r"(a1), "r"(a2), "r"(a3), "r"(b0), "r"(b1));
}
__device__ __forceinline__ unsigned enc_f(float x) {
    unsigned b = __float_as_uint(x);
    return (b & 0x80000000u) ? ~b : (b | 0x80000000u);
}
__device__ __forceinline__ float dec_f(unsigned k) {
    return __uint_as_float((k & 0x80000000u) ? (k & 0x7fffffffu) : ~k);
}

// ---------------------------------------------------------------------------
// Kernel M: bit-pack adjacency at stream bandwidth.
// One thread -> one mask word = 32 CONSECUTIVE adj ints (128 B), loaded as
// 8 independent uint4 (MLP=8), packed with pure ALU, coalesced 4B stores.
//   g_mask[r*256 + s] bit c  <=>  adj[r][s*32 + c] != 0
// ---------------------------------------------------------------------------
__global__ __launch_bounds__(256) void mask_kernel(const int* __restrict__ adj) {
    const size_t w = (size_t)blockIdx.x * 256 + threadIdx.x;  // 0..2M-1
    const uint4* src = (const uint4*)adj + w * 8;
    uint4 v[8];
#pragma unroll
    for (int q = 0; q < 8; q++) v[q] = src[q];  // all 8 loads in flight
    unsigned m = 0;
#pragma unroll
    for (int q = 0; q < 8; q++) {
        m |= (v[q].x != 0 ? 1u : 0u) << (4 * q + 0);
        m |= (v[q].y != 0 ? 1u : 0u) << (4 * q + 1);
        m |= (v[q].z != 0 ? 1u : 0u) << (4 * q + 2);
        m |= (v[q].w != 0 ? 1u : 0u) << (4 * q + 3);
    }
    g_mask[w] = m;
}

// ---------------------------------------------------------------------------
// Kernel A: Wh = h @ W. k-outer/r-inner (Ws reuse across 4 rows).
// ---------------------------------------------------------------------------
__global__ __launch_bounds__(256, 4) void wh_kernel(const float* __restrict__ h,
                                                    const float* __restrict__ W) {
    __shared__ float Ws[128][FOUT];
    if (blockIdx.x == 0 && threadIdx.x == 0) g_gmax_enc = 0u;
    const int f = threadIdx.x & 63;
    const int g = threadIdx.x >> 6;
    const int row0 = blockIdx.x * 16 + g * 4;
    float acc0 = 0.f, acc1 = 0.f, acc2 = 0.f, acc3 = 0.f;
    for (int t = 0; t < 2; t++) {
        __syncthreads();
        for (int idx = threadIdx.x; idx < 128 * FOUT; idx += 256)
            (&Ws[0][0])[idx] = W[t * 128 * FOUT + idx];
        __syncthreads();
        const float4* h0 = (const float4*)(h + (size_t)(row0 + 0) * FIN + t * 128);
        const float4* h1 = (const float4*)(h + (size_t)(row0 + 1) * FIN + t * 128);
        const float4* h2 = (const float4*)(h + (size_t)(row0 + 2) * FIN + t * 128);
        const float4* h3 = (const float4*)(h + (size_t)(row0 + 3) * FIN + t * 128);
#pragma unroll 8
        for (int k4 = 0; k4 < 32; k4++) {
            const float4 v0 = h0[k4], v1 = h1[k4], v2 = h2[k4], v3 = h3[k4];
            const float w0 = Ws[k4 * 4 + 0][f];
            const float w1 = Ws[k4 * 4 + 1][f];
            const float w2 = Ws[k4 * 4 + 2][f];
            const float w3 = Ws[k4 * 4 + 3][f];
            acc0 += v0.x * w0 + v0.y * w1 + v0.z * w2 + v0.w * w3;
            acc1 += v1.x * w0 + v1.y * w1 + v1.z * w2 + v1.w * w3;
            acc2 += v2.x * w0 + v2.y * w1 + v2.z * w2 + v2.w * w3;
            acc3 += v3.x * w0 + v3.y * w1 + v3.z * w2 + v3.w * w3;
        }
    }
    g_Wh[(size_t)(row0 + 0) * FOUT + f] = acc0;
    g_Wh[(size_t)(row0 + 1) * FOUT + f] = acc1;
    g_Wh[(size_t)(row0 + 2) * FOUT + f] = acc2;
    g_Wh[(size_t)(row0 + 3) * FOUT + f] = acc3;
}

// ---------------------------------------------------------------------------
// Kernel B: f_src, E1=exp(f_dst), E2=exp(0.2 f_dst), fused global max(f_dst).
// ---------------------------------------------------------------------------
__global__ __launch_bounds__(256) void fvec_kernel(const float* __restrict__ a) {
    __shared__ unsigned smax[8];
    const int i = blockIdx.x * blockDim.x + threadIdx.x;
    const float4* w4 = (const float4*)(g_Wh + (size_t)i * FOUT);
    const float4* a4 = (const float4*)a;
    float s = 0.f, d = 0.f;
#pragma unroll
    for (int q = 0; q < 16; q++) {
        float4 v = w4[q], as_ = a4[q], ad = a4[16 + q];
        s += v.x * as_.x + v.y * as_.y + v.z * as_.z + v.w * as_.w;
        d += v.x * ad.x + v.y * ad.y + v.z * ad.z + v.w * ad.w;
    }
    g_fsrc[i] = s;
    g_E1[i] = __expf(d);
    g_E2[i] = __expf(0.2f * d);
    unsigned k = enc_f(d);
#pragma unroll
    for (int off = 16; off > 0; off >>= 1)
        k = max(k, __shfl_xor_sync(0xffffffffu, k, off));
    if ((threadIdx.x & 31) == 0) smax[threadIdx.x >> 5] = k;
    __syncthreads();
    if (threadIdx.x == 0) {
        unsigned m = smax[0];
#pragma unroll
        for (int w = 1; w < 8; w++) m = max(m, smax[w]);
        atomicMax(&g_gmax_enc, m);
    }
}

// ---------------------------------------------------------------------------
// Kernel B2: build tf32 B fragments of Wh for mma.m16n8k8.
// ---------------------------------------------------------------------------
__global__ __launch_bounds__(256) void bfrag_kernel() {
    const int wid = blockIdx.x * 8 + (threadIdx.x >> 5);  // 0..4095
    const int lane = threadIdx.x & 31;
    const int jblock = wid >> 3, kh = (wid >> 2) & 1, ntp = wid & 3;
    const int j0 = jblock * 16 + kh * 8;
    const int f0 = ntp * 16;
    const int g = lane >> 2, tc = lane & 3;
    uint4 b;
    b.x = f2tf32(g_Wh[(size_t)(j0 + tc) * FOUT + f0 + g]);
    b.y = f2tf32(g_Wh[(size_t)(j0 + tc + 4) * FOUT + f0 + g]);
    b.z = f2tf32(g_Wh[(size_t)(j0 + tc) * FOUT + f0 + 8 + g]);
    b.w = f2tf32(g_Wh[(size_t)(j0 + tc + 4) * FOUT + f0 + 8 + g]);
    g_Bfrag[(size_t)wid * 32 + lane] = b;
}

// ---------------------------------------------------------------------------
// Kernel C (main): D[128,64] += P[128,1024] @ Wh[1024,64] via mma.tf32.
// adj from bit-packed g_mask (8 MB, L2-resident, read once):
//   per superstep (128 j = 4 steps), each row loads uint4 of 4 mask words;
//   step si uses component si; thread (tc) uses bits tc+4cq.
// No cp.async, no smem adj, no CTA syncs in the loop; masks prefetched one
// superstep ahead.
// ---------------------------------------------------------------------------
__global__ __launch_bounds__(256, 2) void gat_mma_kernel() {
    __shared__ float2 s_E[1024];  // 8 KB
    __shared__ float  sA1[NTILE], sA2[NTILE];

    const int tid = threadIdx.x, lane = tid & 31, warp = tid >> 5;
    const int g = lane >> 2, tc = lane & 3;
    const int it = blockIdx.x >> 3, js = blockIdx.x & 7;
    const int row0 = it * NTILE, jbase = js * 1024;

    // stage E and per-row A1/A2
    for (int k = tid; k < 1024; k += 256)
        s_E[k] = make_float2(g_E1[jbase + k], g_E2[jbase + k]);
    if (tid < NTILE) {
        const float fs = g_fsrc[row0 + tid];
        float M = fs + dec_f(g_gmax_enc);
        M = M > 0.f ? M : 0.2f * M;  // lrelu monotone -> valid row upper bound
        sA1[tid] = __expf(fs - M);
        sA2[tid] = __expf(0.2f * fs - M);
    }
    __syncthreads();

    const int lr0 = warp * 16 + g, lr1 = lr0 + 8;
    const int gr0 = row0 + lr0, gr1 = row0 + lr1;
    const float A1r0 = sA1[lr0], A2r0 = sA2[lr0];
    const float A1r1 = sA1[lr1], A2r1 = sA2[lr1];

    // mask base: word index = r*256 + js*32 + s   (s = step within split)
    const unsigned* mp0 = g_mask + (size_t)gr0 * 256 + js * 32;
    const unsigned* mp1 = g_mask + (size_t)gr1 * 256 + js * 32;

    float d[8][4];
#pragma unroll
    for (int nt = 0; nt < 8; nt++)
#pragma unroll
        for (int q = 0; q < 4; q++) d[nt][q] = 0.f;
    float l0 = 0.f, l1 = 0.f;

    uint4 m40 = *(const uint4*)mp0;
    uint4 m41 = *(const uint4*)mp1;

    for (int sb = 0; sb < NSB; sb++) {
        uint4 n40, n41;
        if (sb < NSB - 1) {  // prefetch next superstep's masks
            n40 = *(const uint4*)(mp0 + (sb + 1) * 4);
            n41 = *(const uint4*)(mp1 + (sb + 1) * 4);
        }
        const unsigned mw0[4] = {m40.x, m40.y, m40.z, m40.w};
        const unsigned mw1[4] = {m41.x, m41.y, m41.z, m41.w};
#pragma unroll
        for (int si = 0; si < 4; si++) {
            const int s = sb * 4 + si;
            const int jl = s * 32;
            const unsigned m0 = mw0[si], m1 = mw1[si];

            // ---- p for 2 rows x 8 cols {tc + 4cq}; bit tc+4cq ----
            float p0[8], p1[8];
#pragma unroll
            for (int cq = 0; cq < 8; cq++) {
                const float2 e = s_E[jl + tc + cq * 4];
                const float v0 = fmaxf(A1r0 * e.x, A2r0 * e.y);
                const float v1 = fmaxf(A1r1 * e.x, A2r1 * e.y);
                p0[cq] = ((m0 >> (tc + 4 * cq)) & 1u) ? v0 : 0.f;
                p1[cq] = ((m1 >> (tc + 4 * cq)) & 1u) ? v1 : 0.f;
                l0 += p0[cq];
                l1 += p1[cq];
            }

            // ---- 4 K-groups of 8 j: MMAs (B fragments from L2) ----
#pragma unroll
            for (int kk = 0; kk < 4; kk++) {
                const int jblock = js * 64 + 2 * s + (kk >> 1);
                const int kh = kk & 1;
                const uint4* bp =
                    &g_Bfrag[(size_t)((jblock * 2 + kh) * 4) * 32 + lane];
                const uint32_t a0 = f2tf32(p0[kk * 2]);
                const uint32_t a1 = f2tf32(p1[kk * 2]);
                const uint32_t a2 = f2tf32(p0[kk * 2 + 1]);
                const uint32_t a3 = f2tf32(p1[kk * 2 + 1]);
                const uint4 B0 = bp[0];
                const uint4 B1 = bp[32];
                const uint4 B2 = bp[64];
                const uint4 B3 = bp[96];
                mma_tf32(d[0], a0, a1, a2, a3, B0.x, B0.y);
                mma_tf32(d[1], a0, a1, a2, a3, B0.z, B0.w);
                mma_tf32(d[2], a0, a1, a2, a3, B1.x, B1.y);
                mma_tf32(d[3], a0, a1, a2, a3, B1.z, B1.w);
                mma_tf32(d[4], a0, a1, a2, a3, B2.x, B2.y);
                mma_tf32(d[5], a0, a1, a2, a3, B2.z, B2.w);
                mma_tf32(d[6], a0, a1, a2, a3, B3.x, B3.y);
                mma_tf32(d[7], a0, a1, a2, a3, B3.z, B3.w);
            }
        }
        m40 = n40;
        m41 = n41;
    }

    // write D partials
#pragma unroll
    for (int nt = 0; nt < 8; nt++) {
        const int f = nt * 8 + 2 * tc;
        *(float2*)&g_Dpart[js][(size_t)gr0 * FOUT + f] =
            make_float2(d[nt][0], d[nt][1]);
        *(float2*)&g_Dpart[js][(size_t)gr1 * FOUT + f] =
            make_float2(d[nt][2], d[nt][3]);
    }
    // row sums: reduce over tc (lanes g*4..g*4+3)
    l0 += __shfl_xor_sync(0xffffffffu, l0, 1);
    l0 += __shfl_xor_sync(0xffffffffu, l0, 2);
    l1 += __shfl_xor_sync(0xffffffffu, l1, 1);
    l1 += __shfl_xor_sync(0xffffffffu, l1, 2);
    if (tc == 0) {
        g_lpart[js][gr0] = l0;
        g_lpart[js][gr1] = l1;
    }
}

// ---------------------------------------------------------------------------
// Kernel E: combine partials, divide, ELU.
// ---------------------------------------------------------------------------
__global__ __launch_bounds__(256) void fixup_kernel(float* __restrict__ out) {
    const int idx = blockIdx.x * 256 + threadIdx.x;
    const int i = idx >> 4;
    const int f4 = (idx & 15) * 4;
    float4 acc = make_float4(0.f, 0.f, 0.f, 0.f);
    float l = 0.f;
#pragma unroll
    for (int js = 0; js < NSPLIT; js++) {
        const float4 dv = *(const float4*)&g_Dpart[js][(size_t)i * FOUT + f4];
        acc.x += dv.x; acc.y += dv.y; acc.z += dv.z; acc.w += dv.w;
        l += g_lpart[js][i];
    }
    const float inv = 1.f / l;
    float o0 = acc.x * inv, o1 = acc.y * inv, o2 = acc.z * inv, o3 = acc.w * inv;
    o0 = o0 > 0.f ? o0 : expm1f(o0);
    o1 = o1 > 0.f ? o1 : expm1f(o1);
    o2 = o2 > 0.f ? o2 : expm1f(o2);
    o3 = o3 > 0.f ? o3 : expm1f(o3);
    *(float4*)&out[(size_t)i * FOUT + f4] = make_float4(o0, o1, o2, o3);
}

// ---------------------------------------------------------------------------
extern "C" void kernel_launch(void* const* d_in, const int* in_sizes, int n_in,
                              void* d_out, int out_size) {
    const float* h = (const float*)d_in[0];
    const int* adj = (const int*)d_in[1];
    const float* W = (const float*)d_in[2];
    const float* a = (const float*)d_in[3];
    float* out = (float*)d_out;

    mask_kernel<<<8192, 256>>>(adj);
    wh_kernel<<<N / 16, 256>>>(h, W);
    fvec_kernel<<<N / 256, 256>>>(a);
    bfrag_kernel<<<512, 256>>>();
    gat_mma_kernel<<<(N / NTILE) * NSPLIT, 256>>>();
    fixup_kernel<<<N * 16 / 256, 256>>>(out);
}